// round 1
// baseline (speedup 1.0000x reference)
#include <cuda_runtime.h>
#include <cstdint>

#define N_BATCH 8
#define K_ANCH  9
#define Hdim    120
#define Wdim    120
#define HW      (Hdim*Wdim)
#define TOT     (HW*K_ANCH)       /* 129600 */
#define PRE     3000
#define POST    300
#define NWORDS  47                /* ceil(3000/64) */
#define MPITCH  48
#define CAND_MAX 8192
#define NBUCKET  4096

// ---------------- scratch (static device globals; no allocation) ------------
__device__ int    g_topk_idx[N_BATCH*PRE];
__device__ float  g_topk_score[N_BATCH*PRE];
__device__ float4 g_boxes[N_BATCH*PRE];
__device__ unsigned long long g_mask[(size_t)N_BATCH*PRE*MPITCH];   // ~9.2MB
__device__ float  g_selscore[N_BATCH*POST];

// monotone float->uint key (descending floats -> descending uints)
__device__ __forceinline__ unsigned int fkey(float x) {
    unsigned int u = __float_as_uint(x);
    return (u & 0x80000000u) ? ~u : (u | 0x80000000u);
}
__device__ __forceinline__ float fkey_inv(unsigned int k) {
    return (k & 0x80000000u) ? __uint_as_float(k ^ 0x80000000u)
                             : __uint_as_float(~k);
}

// ---------------- Stage 1: per-batch exact top-3000 -------------------------
// 8 blocks x 1024 threads. Radix-histogram threshold (12-bit buckets) then
// bitonic sort of candidates (<=8192) on packed (key<<32 | ~idx) u64.
extern "C" __global__ void __launch_bounds__(1024)
topk_kernel(const float* __restrict__ cls) {
    extern __shared__ unsigned long long s_cand[];   // 8192 * 8B = 64KB
    __shared__ unsigned int hist[NBUCKET];           // 16KB
    __shared__ unsigned int psum[1024];              // 4KB
    __shared__ unsigned int s_B;
    __shared__ unsigned int s_cnt;

    const int n   = blockIdx.x;
    const int tid = threadIdx.x;
    const float* sc = cls + (size_t)n * TOT;

    for (int b = tid; b < NBUCKET; b += 1024) hist[b] = 0;
    if (tid == 0) s_cnt = 0;
    __syncthreads();

    for (int i = tid; i < TOT; i += 1024)
        atomicAdd(&hist[fkey(sc[i]) >> 20], 1u);
    __syncthreads();

    psum[tid] = hist[4*tid] + hist[4*tid+1] + hist[4*tid+2] + hist[4*tid+3];
    __syncthreads();

    if (tid == 0) {
        unsigned int acc = 0;
        int S = 0;
        for (int s = 31; s >= 0; --s) {
            unsigned int q = 0;
            for (int t = 0; t < 32; ++t) q += psum[s*32 + t];
            if (acc + q >= PRE) { S = s; break; }
            acc += q;
        }
        int Pb = S*32;
        for (int t = 31; t >= 0; --t) {
            unsigned int q = psum[S*32 + t];
            if (acc + q >= PRE) { Pb = S*32 + t; break; }
            acc += q;
        }
        unsigned int B = (unsigned int)(Pb*4);
        for (int b = 3; b >= 0; --b) {
            unsigned int q = hist[Pb*4 + b];
            if (acc + q >= PRE) { B = (unsigned int)(Pb*4 + b); break; }
            acc += q;
        }
        s_B = B;
    }
    __syncthreads();

    const unsigned int thr = s_B << 20;
    for (int i = tid; i < TOT; i += 1024) {
        unsigned int k = fkey(sc[i]);
        if (k >= thr) {
            unsigned int pos = atomicAdd(&s_cnt, 1u);
            if (pos < CAND_MAX)
                s_cand[pos] = ((unsigned long long)k << 32) |
                              (unsigned int)(~(unsigned int)i);
        }
    }
    __syncthreads();

    const unsigned int cnt = s_cnt;               // guaranteed >= PRE
    const int S_sort = (cnt <= 4096u) ? 4096 : 8192;
    for (int i = (int)cnt + tid; i < S_sort; i += 1024) s_cand[i] = 0ull;
    __syncthreads();

    // bitonic sort, descending on u64 (ties: smaller idx first via ~idx)
    for (int k = 2; k <= S_sort; k <<= 1) {
        for (int j = k >> 1; j > 0; j >>= 1) {
            for (int i = tid; i < S_sort; i += 1024) {
                int ixj = i ^ j;
                if (ixj > i) {
                    unsigned long long a = s_cand[i], b = s_cand[ixj];
                    bool dir = (i & k) != 0;      // true => ascending segment
                    if ((a < b) != dir) { s_cand[i] = b; s_cand[ixj] = a; }
                }
            }
            __syncthreads();
        }
    }

    for (int r = tid; r < PRE; r += 1024) {
        unsigned long long c = s_cand[r];
        unsigned int key = (unsigned int)(c >> 32);
        int idx = (int)(~(unsigned int)(c & 0xFFFFFFFFull));
        g_topk_idx[n*PRE + r]   = idx;
        g_topk_score[n*PRE + r] = fkey_inv(key);
    }
}

// ---------------- Stage 2: gather-compute selected boxes --------------------
// Selected q-index o is interpreted in the regions p-layout:
//   o = (hh*W + ww)*K + kk;  flat F = o*4 + jj  maps (via reshape) to
//   f = ((kk*4+jj)*H + hh)*W + ww  over original (h,w,k,j) with
//   f = ((h*W + w)*K + k)*4 + j;  value = anchor(h,w,k,j) + delta, clipped.
extern "C" __global__ void boxes_kernel(const float* __restrict__ deltas) {
    int g = blockIdx.x*blockDim.x + threadIdx.x;
    if (g >= N_BATCH*PRE) return;
    const int n = g / PRE;
    const int o = g_topk_idx[g];

    const int kk = o % K_ANCH;
    const int t0 = o / K_ANCH;
    const int ww = t0 % Wdim;
    const int hh = t0 / Wdim;

    const float ratios_[3] = {0.5f, 1.0f, 2.0f};
    const float scales_[3] = {8.0f, 16.0f, 32.0f};

    float v[4];
#pragma unroll
    for (int jj = 0; jj < 4; ++jj) {
        int f  = ((kk*4 + jj)*Hdim + hh)*Wdim + ww;
        int j  = f & 3;
        int r1 = f >> 2;
        int k  = r1 % K_ANCH;
        int r2 = r1 / K_ANCH;
        int w  = r2 % Wdim;
        int h  = r2 / Wdim;

        float sr  = __fsqrt_rn(ratios_[k/3]);
        float wsz = __fdiv_rn(__fmul_rn(16.0f, scales_[k%3]), sr);
        float hsz = __fmul_rn(__fmul_rn(16.0f, scales_[k%3]), sr);
        float cx  = __fmul_rn(__fadd_rn((float)w, 0.5f), 16.0f);
        float cy  = __fmul_rn(__fadd_rn((float)h, 0.5f), 16.0f);

        float a;
        if      (j == 0) a = __fsub_rn(cx, __fmul_rn(0.5f, wsz));
        else if (j == 1) a = __fsub_rn(cy, __fmul_rn(0.5f, hsz));
        else if (j == 2) a = __fadd_rn(cx, __fmul_rn(0.5f, wsz));
        else             a = __fadd_rn(cy, __fmul_rn(0.5f, hsz));

        float d   = deltas[((size_t)n*36 + (k*4 + j))*HW + h*Wdim + w];
        float val = __fadd_rn(a, d);
        v[jj] = fminf(fmaxf(val, 0.0f), 1919.0f);
    }
    g_boxes[g] = make_float4(v[0], v[1], v[2], v[3]);
}

// ---------------- Stage 3: NMS suppression bitmask --------------------------
// grid (47,47,8), 64 threads. Row-block rb, col-block cb (upper triangle).
extern "C" __global__ void mask_kernel() {
    const int rb = blockIdx.x, cb = blockIdx.y, n = blockIdx.z;
    if (cb < rb) return;
    __shared__ float4 colbox[64];
    const int tid = threadIdx.x;
    const int cj = cb*64 + tid;
    colbox[tid] = (cj < PRE) ? g_boxes[n*PRE + cj] : make_float4(0,0,0,0);
    __syncthreads();

    const int i = rb*64 + tid;
    if (i >= PRE) return;
    const float4 bi = g_boxes[n*PRE + i];
    const float ai = __fmul_rn(__fadd_rn(__fsub_rn(bi.z, bi.x), 1.0f),
                               __fadd_rn(__fsub_rn(bi.w, bi.y), 1.0f));
    unsigned long long bits = 0ull;
    const int jmax = min(64, PRE - cb*64);
    for (int c = 0; c < jmax; ++c) {
        int j = cb*64 + c;
        if (j <= i) continue;
        float4 bj = colbox[c];
        float aj = __fmul_rn(__fadd_rn(__fsub_rn(bj.z, bj.x), 1.0f),
                             __fadd_rn(__fsub_rn(bj.w, bj.y), 1.0f));
        float xx1 = fmaxf(bi.x, bj.x), yy1 = fmaxf(bi.y, bj.y);
        float xx2 = fminf(bi.z, bj.z), yy2 = fminf(bi.w, bj.w);
        float iw = fmaxf(__fadd_rn(__fsub_rn(xx2, xx1), 1.0f), 0.0f);
        float ih = fmaxf(__fadd_rn(__fsub_rn(yy2, yy1), 1.0f), 0.0f);
        float inter = __fmul_rn(iw, ih);
        float denom = __fsub_rn(__fadd_rn(ai, aj), inter);
        float iou   = __fdiv_rn(inter, denom);
        if (iou > 0.5f) bits |= (1ull << c);
    }
    g_mask[((size_t)n*PRE + i)*MPITCH + cb] = bits;
}

// ---------------- Stage 4: sequential scan (early stop at 300 kept) ---------
extern "C" __global__ void scan_kernel(float* __restrict__ out) {
    const int n = blockIdx.x;
    const int tid = threadIdx.x;   // 64 threads
    __shared__ unsigned long long rem[NWORDS];
    __shared__ int s_i;

    for (int r = tid; r < POST; r += 64) {
        g_selscore[n*POST + r] = 0.0f;
        float* o = out + (size_t)(n*POST + r)*5;
        o[1] = 0.0f; o[2] = 0.0f; o[3] = 0.0f; o[4] = 0.0f;
    }
    if (tid < NWORDS)
        rem[tid] = (tid == NWORDS-1) ? ((1ull << 56) - 1ull) : ~0ull;
    __syncthreads();

    int nk = 0;
    int wstart = 0;                 // only tid 0 uses this
    while (true) {
        if (tid == 0) {
            int found = -1;
            int w = wstart;
            for (; w < NWORDS; ++w) {
                unsigned long long cur = rem[w];
                if (cur) {
                    int b = __ffsll((long long)cur) - 1;
                    found = w*64 + b;
                    rem[w] = cur & (cur - 1ull);   // consume bit i
                    break;
                }
            }
            wstart = (w < NWORDS) ? w : NWORDS;
            s_i = found;
        }
        __syncthreads();
        const int i = s_i;
        if (i < 0) break;

        if (tid == 0) {
            float4 b = g_boxes[n*PRE + i];
            float* o = out + (size_t)(n*POST + nk)*5;
            o[1] = b.x; o[2] = b.y; o[3] = b.z; o[4] = b.w;
            g_selscore[n*POST + nk] = g_topk_score[n*PRE + i];
        }
        const int wlo = i >> 6;
        if (tid < NWORDS && tid >= wlo)
            rem[tid] &= ~g_mask[((size_t)n*PRE + i)*MPITCH + tid];

        ++nk;
        if (nk >= POST) break;
        __syncthreads();
    }
}

// ---------------- Stage 5: score column = batch 7's selected scores ---------
extern "C" __global__ void final_kernel(float* __restrict__ out) {
    int g = blockIdx.x*blockDim.x + threadIdx.x;
    if (g >= N_BATCH*POST) return;
    int r = g % POST;
    out[(size_t)g*5] = g_selscore[7*POST + r];
}

// ---------------- launch -----------------------------------------------------
extern "C" void kernel_launch(void* const* d_in, const int* in_sizes, int n_in,
                              void* d_out, int out_size) {
    const float* cls;
    const float* deltas;
    if (in_sizes[0] == N_BATCH*K_ANCH*HW) {     // 1,036,800
        cls = (const float*)d_in[0]; deltas = (const float*)d_in[1];
    } else {
        cls = (const float*)d_in[1]; deltas = (const float*)d_in[0];
    }
    float* out = (float*)d_out;

    cudaFuncSetAttribute(topk_kernel,
                         cudaFuncAttributeMaxDynamicSharedMemorySize, 65536);

    topk_kernel<<<N_BATCH, 1024, 65536>>>(cls);
    boxes_kernel<<<(N_BATCH*PRE + 255)/256, 256>>>(deltas);
    dim3 mg(NWORDS, NWORDS, N_BATCH);
    mask_kernel<<<mg, 64>>>();
    scan_kernel<<<N_BATCH, 64>>>(out);
    final_kernel<<<(N_BATCH*POST + 255)/256, 256>>>(out);
}